// round 17
// baseline (speedup 1.0000x reference)
#include <cuda_runtime.h>
#include <cuda_fp16.h>

#define N_POINTS    32768
#define EMB         64
#define NUM_CLASSES 50
#define NUM_HOUSES  5
#define NUM_WIN     6            // NUM_WINDOWS + 1 (last = frame)
#define BOXES       (NUM_HOUSES * NUM_WIN)   // 30

// Output: data (N*64) | contains (50*N) | dists (50*30*N)
#define OUT_CONTAINS ((size_t)N_POINTS * EMB)
#define OUT_DISTS    (OUT_CONTAINS + (size_t)NUM_CLASSES * N_POINTS)

typedef unsigned int u32;

__device__ __forceinline__ u32 h2max(u32 a, u32 b) {
    u32 r; asm("max.f16x2 %0, %1, %2;" : "=r"(r) : "r"(a), "r"(b)); return r;
}
__device__ __forceinline__ u32 h2min(u32 a, u32 b) {
    u32 r; asm("min.f16x2 %0, %1, %2;" : "=r"(r) : "r"(a), "r"(b)); return r;
}
__device__ __forceinline__ u32 h2sub(u32 a, u32 b) {
    u32 r; asm("sub.rn.f16x2 %0, %1, %2;" : "=r"(r) : "r"(a), "r"(b)); return r;
}
__device__ __forceinline__ u32 h2add(u32 a, u32 b) {
    u32 r; asm("add.rn.f16x2 %0, %1, %2;" : "=r"(r) : "r"(a), "r"(b)); return r;
}
__device__ __forceinline__ u32 h2fma(u32 a, u32 b, u32 c) {
    u32 r; asm("fma.rn.f16x2 %0, %1, %2, %3;" : "=r"(r) : "r"(a), "r"(b), "r"(c)); return r;
}
__device__ __forceinline__ u32 h2mul(u32 a, u32 b) {
    u32 r; asm("mul.rn.f16x2 %0, %1, %2;" : "=r"(r) : "r"(a), "r"(b)); return r;
}
// pack two f32 -> f16x2 (lo in low half). cvt d, a, b: d.hi=a, d.lo=b.
__device__ __forceinline__ u32 packh2(float lo, float hi) {
    u32 r; asm("cvt.rn.f16x2.f32 %0, %1, %2;" : "=r"(r) : "f"(hi), "f"(lo)); return r;
}
__device__ __forceinline__ void h2tof32(u32 v, float& x, float& y) {
    asm("{\n\t.reg .b16 l, h;\n\tmov.b32 {l, h}, %2;\n\t"
        "cvt.f32.f16 %0, l;\n\tcvt.f32.f16 %1, h;\n\t}"
        : "=f"(x), "=f"(y) : "r"(v));
}

// One 2-dim fp16x2 step: clamp (HMNMX2 x2, alu) + sub + fma (fma pipe).
#define H2STEP_FMA(P, LO, HI, ACC) {                              \
    const u32 _d = h2sub((P), h2min(h2max((P), (LO)), (HI)));     \
    (ACC) = h2fma(_d, _d, (ACC)); }
#define H2STEP_MUL(P, LO, HI, ACC) {                              \
    const u32 _d = h2sub((P), h2min(h2max((P), (LO)), (HI)));     \
    (ACC) = h2mul(_d, _d); }

#define SLOT_STRIDE 9   // 8 data uint4 + 1 pad -> 144B group skew (4 banks)

__global__ __launch_bounds__(256, 2)
void geom_kernel(const float* __restrict__ data,
                 const float* __restrict__ shape,   // [50][5][6][2][64]
                 float* __restrict__ out)
{
    __shared__ uint4 s_box[BOXES][2 * SLOT_STRIDE];

    const int c   = blockIdx.y;
    const int tid = threadIdx.x;

    // ---- stage this class's 30 boxes as fp16x2 lo/hi pairs ----
    const float* sb = shape + (size_t)c * (BOXES * 2 * EMB);
    #pragma unroll
    for (int e = tid; e < BOXES * 16; e += 256) {
        const int box = e >> 4;
        const int s   = e & 15;           // slot: 4 dims
        const int d   = (s >> 3) * 32 + (s & 7) * 4;
        const float4 a = *reinterpret_cast<const float4*>(sb + box * 128 + d);
        const float4 b = *reinterpret_cast<const float4*>(sb + box * 128 + 64 + d);
        uint4 v;
        v.x = packh2(fminf(a.x, b.x), fminf(a.y, b.y));
        v.y = packh2(fmaxf(a.x, b.x), fmaxf(a.y, b.y));
        v.z = packh2(fminf(a.z, b.z), fminf(a.w, b.w));
        v.w = packh2(fmaxf(a.z, b.z), fmaxf(a.w, b.w));
        s_box[box][(s >> 3) * SLOT_STRIDE + (s & 7)] = v;
    }

    // ---- data passthrough (class-slice 0 only): linear block copy ----
    if (blockIdx.y == 0) {
        // this block covers 512 points = 32768 floats = 8192 float4
        const float4* src = reinterpret_cast<const float4*>(
            data + (size_t)blockIdx.x * 512 * EMB);
        float4* dst = reinterpret_cast<float4*>(
            out + (size_t)blockIdx.x * 512 * EMB);
        #pragma unroll
        for (int k = 0; k < 32; k++)
            dst[tid + 256 * k] = src[tid + 256 * k];
    }
    __syncthreads();

    // ---- 2 threads per point, 4 points per thread: 64 points/warp ----
    const int lane = tid & 31;
    const int warp = tid >> 5;
    const int g    = lane >> 4;   // dim group: dims [g*32, g*32+32)
    const int i    = lane & 15;
    const int n0   = blockIdx.x * 512 + warp * 64 + i;  // +16, +32, +48

    // 32 dims per point = 16 f16x2 pairs, four points
    u32 p[4][16];
    #pragma unroll
    for (int pt = 0; pt < 4; pt++) {
        const float4* dp = reinterpret_cast<const float4*>(
            data + (size_t)(n0 + 16 * pt) * EMB + g * 32);
        #pragma unroll
        for (int k = 0; k < 8; k++) {
            const float4 v = dp[k];
            p[pt][2 * k]     = packh2(v.x, v.y);
            p[pt][2 * k + 1] = packh2(v.z, v.w);
        }
    }

    // dual-store: g==0 half stores points n0, n0+16; g==1 stores n0+32, n0+48.
    float* __restrict__ out_dists = out + OUT_DISTS
                                  + (size_t)c * BOXES * N_POINTS + n0
                                  + g * 32;

    bool town[4]  = {false, false, false, false};
    bool anyw[4], frame[4];
    #pragma unroll 1
    for (int h = 0; h < NUM_HOUSES; h++) {
        #pragma unroll
        for (int pt = 0; pt < 4; pt++) { anyw[pt] = false; frame[pt] = false; }
        #pragma unroll 1
        for (int w = 0; w < NUM_WIN; w++) {
            const int box = h * NUM_WIN + w;
            const uint4* bx = &s_box[box][g * SLOT_STRIDE];
            // 8 accumulator chains (2 per point), depth 8
            u32 acc0[4], acc1[4];
            {
                const uint4 q = bx[0];
                #pragma unroll
                for (int pt = 0; pt < 4; pt++) {
                    H2STEP_MUL(p[pt][0], q.x, q.y, acc0[pt])
                    H2STEP_MUL(p[pt][1], q.z, q.w, acc1[pt])
                }
            }
            #pragma unroll
            for (int k = 1; k < 8; k++) {
                const uint4 q = bx[k];
                #pragma unroll
                for (int pt = 0; pt < 4; pt++) {
                    H2STEP_FMA(p[pt][2 * k],     q.x, q.y, acc0[pt])
                    H2STEP_FMA(p[pt][2 * k + 1], q.z, q.w, acc1[pt])
                }
            }
            // combine chains, widen to fp32, cross-half reduce
            float sq[4];
            #pragma unroll
            for (int pt = 0; pt < 4; pt++) {
                const u32 s = h2add(acc0[pt], acc1[pt]);
                float x, y; h2tof32(s, x, y);
                sq[pt] = x + y;
                sq[pt] += __shfl_xor_sync(0xffffffffu, sq[pt], 16);
            }
            // inside <=> all fp16 deltas 0 <=> sq == 0 (partials >= 0)
            #pragma unroll
            for (int pt = 0; pt < 4; pt++) {
                const bool ins = (sq[pt] == 0.0f);
                if (w < NUM_WIN - 1) anyw[pt] |= ins;
                else                 frame[pt] = ins;
            }
            // each half stores its own two points
            const float sqm0 = g ? sq[2] : sq[0];
            const float sqm1 = g ? sq[3] : sq[1];
            float d0, d1;
            asm("sqrt.approx.f32 %0, %1;" : "=f"(d0) : "f"(sqm0));
            asm("sqrt.approx.f32 %0, %1;" : "=f"(d1) : "f"(sqm1));
            out_dists[(size_t)box * N_POINTS]      = d0;
            out_dists[(size_t)box * N_POINTS + 16] = d1;
        }
        #pragma unroll
        for (int pt = 0; pt < 4; pt++)
            town[pt] |= (frame[pt] && !anyw[pt]);
    }

    // contains: each half stores its own two points
    const bool tm0 = g ? town[2] : town[0];
    const bool tm1 = g ? town[3] : town[1];
    out[OUT_CONTAINS + (size_t)c * N_POINTS + n0 + g * 32]      = tm0 ? 1.0f : 0.0f;
    out[OUT_CONTAINS + (size_t)c * N_POINTS + n0 + g * 32 + 16] = tm1 ? 1.0f : 0.0f;
}

extern "C" void kernel_launch(void* const* d_in, const int* in_sizes, int n_in,
                              void* d_out, int out_size) {
    const float* data  = (const float*)d_in[0];
    const float* shape = (const float*)d_in[1];
    float* out = (float*)d_out;

    dim3 grid(N_POINTS / 512, NUM_CLASSES);
    geom_kernel<<<grid, 256>>>(data, shape, out);
}